// round 2
// baseline (speedup 1.0000x reference)
#include <cuda_runtime.h>
#include <math.h>

// ---------------------------------------------------------------------------
// MultiScaleHyperGenerator: 7-layer grouped 3x3 conv chain, B=16 groups.
//   head : [16,3,256,256] (zero-pad 7)  -> [16,64,268,268], leaky_relu(0.02)
//   body0..4 : 64->64 VALID 3x3, leaky_relu     268->266->264->262->260->258
//   tail : 64->3 VALID 3x3, tanh        -> [16,3,256,256]
// norm_weight folds to scalars: out = cw*conv(x,w) + cb*b
// ---------------------------------------------------------------------------

#define BATCH 16
#define NFEAT 64

// ping-pong scratch: [16, 64, 268, 268] floats = 294 MB each
__device__ float g_buf0[16u * 64u * 268u * 268u];
__device__ float g_buf1[16u * 64u * 268u * 268u];

// ---------------------------------------------------------------------------
// Head: IC=3 with implicit zero-padding of 7 around the 256x256 noise.
// Block: 256 thr = 32x8 output tile, 16 out-channels per block.
// ---------------------------------------------------------------------------
__global__ __launch_bounds__(256)
void head_kernel(const float* __restrict__ noise,   // [16,3,256,256]
                 const float* __restrict__ hw,      // [16,64,3,3,3]
                 const float* __restrict__ hb,      // [16,64]
                 float* __restrict__ out,           // [16,64,268,268]
                 float cw, float cb)
{
    const int Sout = 268;
    int b   = blockIdx.z >> 2;
    int oc0 = (blockIdx.z & 3) << 4;
    int tx0 = blockIdx.x * 32, ty0 = blockIdx.y * 8;
    int tid = threadIdx.x, tx = tid & 31, ty = tid >> 5;

    __shared__ __align__(16) float ws[3 * 9 * 16];  // [ic][k][oc]
    __shared__ float xs[3 * 10 * 34];                // [ic][10][34]

    for (int i = tid; i < 3 * 144; i += 256) {
        int oc = i & 15, k = (i >> 4) % 9, ic = i / 144;
        ws[i] = hw[((b * 64 + oc0 + oc) * 3 + ic) * 9 + k];
    }
    for (int i = tid; i < 3 * 340; i += 256) {
        int ic = i / 340, rem = i % 340, r = rem / 34, c = rem % 34;
        int gy = ty0 + r - 7, gx = tx0 + c - 7;
        float v = 0.f;
        if (gy >= 0 && gy < 256 && gx >= 0 && gx < 256)
            v = noise[((size_t)(b * 3 + ic) * 256 + gy) * 256 + gx];
        xs[i] = v;
    }
    __syncthreads();

    float acc[16];
#pragma unroll
    for (int o = 0; o < 16; o++) acc[o] = 0.f;

#pragma unroll
    for (int ic = 0; ic < 3; ic++) {
        const float* xp = xs + ic * 340 + ty * 34 + tx;
        float xv[9];
#pragma unroll
        for (int ky = 0; ky < 3; ky++)
#pragma unroll
            for (int kx = 0; kx < 3; kx++)
                xv[ky * 3 + kx] = xp[ky * 34 + kx];
        const float4* wp = (const float4*)(ws + ic * 144);
#pragma unroll
        for (int k = 0; k < 9; k++) {
#pragma unroll
            for (int q = 0; q < 4; q++) {
                float4 w4 = wp[k * 4 + q];
                acc[q * 4 + 0] = fmaf(xv[k], w4.x, acc[q * 4 + 0]);
                acc[q * 4 + 1] = fmaf(xv[k], w4.y, acc[q * 4 + 1]);
                acc[q * 4 + 2] = fmaf(xv[k], w4.z, acc[q * 4 + 2]);
                acc[q * 4 + 3] = fmaf(xv[k], w4.w, acc[q * 4 + 3]);
            }
        }
    }

    int ox = tx0 + tx, oy = ty0 + ty;
    if (ox < Sout && oy < Sout) {
        size_t obase = ((size_t)(b * 64 + oc0)) * Sout * Sout + (size_t)oy * Sout + ox;
#pragma unroll
        for (int o = 0; o < 16; o++) {
            float v = acc[o] * cw + hb[b * 64 + oc0 + o] * cb;
            v = v > 0.f ? v : 0.02f * v;
            out[obase + (size_t)o * Sout * Sout] = v;
        }
    }
}

// ---------------------------------------------------------------------------
// Body: IC=OC=64, VALID, leaky_relu. 256 thr = 32x8 tile, 16 oc per block.
// All 16x64x9 weights staged in smem [ic][k][oc] (36 KB); input staged
// 8 ic-planes at a time (10x34 tiles, 10.6 KB). Total 47.7 KB static smem.
// ---------------------------------------------------------------------------
__global__ __launch_bounds__(256)
void body_kernel(const float* __restrict__ in,     // [16,64,Sin,Sin]
                 const float* __restrict__ w,      // [16,64,64,3,3]
                 const float* __restrict__ bias,   // [16,64]
                 float* __restrict__ out,          // [16,64,Sout,Sout]
                 int Sin, float cw, float cb)
{
    const int Sout = Sin - 2;
    int b   = blockIdx.z >> 2;
    int oc0 = (blockIdx.z & 3) << 4;
    int tx0 = blockIdx.x * 32, ty0 = blockIdx.y * 8;
    int tid = threadIdx.x, tx = tid & 31, ty = tid >> 5;

    __shared__ __align__(16) float ws[64 * 9 * 16]; // [ic][k][oc]  36 KB
    __shared__ float xs[8 * 340];                    // 8 planes [10][34]

    for (int i = tid; i < 64 * 144; i += 256) {
        int oc = i & 15, k = (i >> 4) % 9, ic = i / 144;
        ws[i] = w[((b * 64 + oc0 + oc) * 64 + ic) * 9 + k];
    }

    float acc[16];
#pragma unroll
    for (int o = 0; o < 16; o++) acc[o] = 0.f;

    const float* inb = in + (size_t)b * 64 * Sin * Sin;

    for (int ics = 0; ics < 64; ics += 8) {
        __syncthreads();
        for (int i = tid; i < 8 * 340; i += 256) {
            int icl = i / 340, rem = i % 340, r = rem / 34, c = rem % 34;
            int gy = ty0 + r, gx = tx0 + c;
            float v = 0.f;
            if (gy < Sin && gx < Sin)
                v = inb[(size_t)(ics + icl) * Sin * Sin + (size_t)gy * Sin + gx];
            xs[i] = v;
        }
        __syncthreads();

#pragma unroll
        for (int icl = 0; icl < 8; icl++) {
            const float* xp = xs + icl * 340 + ty * 34 + tx;
            float xv[9];
#pragma unroll
            for (int ky = 0; ky < 3; ky++)
#pragma unroll
                for (int kx = 0; kx < 3; kx++)
                    xv[ky * 3 + kx] = xp[ky * 34 + kx];
            const float4* wp = (const float4*)(ws + (ics + icl) * 144);
#pragma unroll
            for (int k = 0; k < 9; k++) {
#pragma unroll
                for (int q = 0; q < 4; q++) {
                    float4 w4 = wp[k * 4 + q];
                    acc[q * 4 + 0] = fmaf(xv[k], w4.x, acc[q * 4 + 0]);
                    acc[q * 4 + 1] = fmaf(xv[k], w4.y, acc[q * 4 + 1]);
                    acc[q * 4 + 2] = fmaf(xv[k], w4.z, acc[q * 4 + 2]);
                    acc[q * 4 + 3] = fmaf(xv[k], w4.w, acc[q * 4 + 3]);
                }
            }
        }
    }

    int ox = tx0 + tx, oy = ty0 + ty;
    if (ox < Sout && oy < Sout) {
        size_t obase = ((size_t)(b * 64 + oc0)) * Sout * Sout + (size_t)oy * Sout + ox;
#pragma unroll
        for (int o = 0; o < 16; o++) {
            float v = acc[o] * cw + bias[b * 64 + oc0 + o] * cb;
            v = v > 0.f ? v : 0.02f * v;
            out[obase + (size_t)o * Sout * Sout] = v;
        }
    }
}

// ---------------------------------------------------------------------------
// Tail: IC=64, OC=3, tanh. 256 thr = 32x8 tile, all 3 oc in one block.
// ---------------------------------------------------------------------------
__global__ __launch_bounds__(256)
void tail_kernel(const float* __restrict__ in,     // [16,64,258,258]
                 const float* __restrict__ w,      // [16,3,64,3,3]
                 const float* __restrict__ bias,   // [16,3]
                 float* __restrict__ out,          // [16,3,256,256]
                 float cw, float cb)
{
    const int Sin = 258, Sout = 256;
    int b   = blockIdx.z;
    int tx0 = blockIdx.x * 32, ty0 = blockIdx.y * 8;
    int tid = threadIdx.x, tx = tid & 31, ty = tid >> 5;

    __shared__ float ws[64 * 9 * 3];  // [ic][k][oc]
    __shared__ float xs[8 * 340];

    for (int i = tid; i < 64 * 27; i += 256) {
        int oc = i % 3, k = (i / 3) % 9, ic = i / 27;
        ws[i] = w[((b * 3 + oc) * 64 + ic) * 9 + k];
    }

    float acc[3] = {0.f, 0.f, 0.f};
    const float* inb = in + (size_t)b * 64 * Sin * Sin;

    for (int ics = 0; ics < 64; ics += 8) {
        __syncthreads();
        for (int i = tid; i < 8 * 340; i += 256) {
            int icl = i / 340, rem = i % 340, r = rem / 34, c = rem % 34;
            int gy = ty0 + r, gx = tx0 + c;
            float v = 0.f;
            if (gy < Sin && gx < Sin)
                v = inb[(size_t)(ics + icl) * Sin * Sin + (size_t)gy * Sin + gx];
            xs[i] = v;
        }
        __syncthreads();

#pragma unroll
        for (int icl = 0; icl < 8; icl++) {
            const float* xp = xs + icl * 340 + ty * 34 + tx;
            float xv[9];
#pragma unroll
            for (int ky = 0; ky < 3; ky++)
#pragma unroll
                for (int kx = 0; kx < 3; kx++)
                    xv[ky * 3 + kx] = xp[ky * 34 + kx];
            const float* wp = ws + (ics + icl) * 27;
#pragma unroll
            for (int k = 0; k < 9; k++) {
#pragma unroll
                for (int o = 0; o < 3; o++)
                    acc[o] = fmaf(xv[k], wp[k * 3 + o], acc[o]);
            }
        }
    }

    int ox = tx0 + tx, oy = ty0 + ty;
    if (ox < Sout && oy < Sout) {
        size_t obase = ((size_t)(b * 3)) * Sout * Sout + (size_t)oy * Sout + ox;
#pragma unroll
        for (int o = 0; o < 3; o++) {
            float v = tanhf(acc[o] * cw + bias[b * 3 + o] * cb);
            out[obase + (size_t)o * Sout * Sout] = v;
        }
    }
}

// ---------------------------------------------------------------------------
extern "C" void kernel_launch(void* const* d_in, const int* in_sizes, int n_in,
                              void* d_out, int out_size)
{
    const float* noise  = (const float*)d_in[0];
    const float* head_w = (const float*)d_in[1];
    const float* head_b = (const float*)d_in[2];
    const float* body_w = (const float*)d_in[3];
    const float* body_b = (const float*)d_in[4];
    const float* tail_w = (const float*)d_in[5];
    const float* tail_b = (const float*)d_in[6];
    float* out = (float*)d_out;

    float *buf0 = nullptr, *buf1 = nullptr;
    cudaGetSymbolAddress((void**)&buf0, g_buf0);
    cudaGetSymbolAddress((void**)&buf1, g_buf1);

    const double lr_gain = sqrt(2.0 / (1.0 + 0.02 * 0.02));
    const float cw_head = (float)(lr_gain / sqrt(27.0));
    const float cb_head = (float)(1.0 / sqrt(3.0));
    const float cw_body = (float)(lr_gain / 24.0);
    const float cb_body = 0.125f;
    const float cw_tail = (float)((5.0 / 3.0) / 24.0);
    const float cb_tail = 0.125f;

    // head: noise -> buf0 (268)
    {
        dim3 grid((268 + 31) / 32, (268 + 7) / 8, BATCH * 4);
        head_kernel<<<grid, 256>>>(noise, head_w, head_b, buf0, cw_head, cb_head);
    }

    // 5 body layers, ping-pong
    float* src = buf0;
    float* dst = buf1;
    int Sin = 268;
    for (int i = 0; i < 5; i++) {
        int Sout = Sin - 2;
        dim3 grid((Sout + 31) / 32, (Sout + 7) / 8, BATCH * 4);
        const float* wi = body_w + (size_t)i * 16 * 64 * 64 * 9;
        const float* bi = body_b + (size_t)i * 16 * 64;
        body_kernel<<<grid, 256>>>(src, wi, bi, dst, Sin, cw_body, cb_body);
        float* t = src; src = dst; dst = t;
        Sin = Sout;
    }

    // tail: src(258) -> out (256)
    {
        dim3 grid(256 / 32, 256 / 8, BATCH);
        tail_kernel<<<grid, 256>>>(src, tail_w, tail_b, out, cw_tail, cb_tail);
    }
}

// round 5
// speedup vs baseline: 4.3621x; 4.3621x over previous
#include <cuda_runtime.h>
#include <cuda_bf16.h>
#include <math.h>
#include <stdint.h>

#define BATCH 16
#define MAXPIX (268u * 268u)

// activations NHWC, packed (bf16 hi) | (bf16 lo << 16), ping-pong
__device__ unsigned g_hlA[16u * MAXPIX * 64u];
__device__ unsigned g_hlB[16u * MAXPIX * 64u];
// fp32 NHWC buffer feeding the tail (258x258)
__device__ float g_f32[16u * 258u * 258u * 64u];
// pre-split body weights, K-MAJOR: [5][16][tap 9][ic 64][oc 64] bf16
__device__ __nv_bfloat16 g_wth[5u * 16u * 9u * 64u * 64u];
__device__ __nv_bfloat16 g_wtl[5u * 16u * 9u * 64u * 64u];

// ---------------- helpers ----------------
__device__ __forceinline__ uint32_t smem_u32(const void* p) {
    uint32_t a;
    asm("{ .reg .u64 t; cvta.to.shared.u64 t, %1; cvt.u32.u64 %0, t; }" : "=r"(a) : "l"(p));
    return a;
}
__device__ __forceinline__ uint32_t swz(uint32_t o) { return o ^ ((o >> 3) & 0x70); }

__device__ __forceinline__ void ldsm4(uint32_t r[4], uint32_t addr) {
    asm volatile("ldmatrix.sync.aligned.m8n8.x4.shared.b16 {%0,%1,%2,%3}, [%4];"
        : "=r"(r[0]), "=r"(r[1]), "=r"(r[2]), "=r"(r[3]) : "r"(addr));
}
__device__ __forceinline__ void ldsm4t(uint32_t r[4], uint32_t addr) {
    asm volatile("ldmatrix.sync.aligned.m8n8.x4.trans.shared.b16 {%0,%1,%2,%3}, [%4];"
        : "=r"(r[0]), "=r"(r[1]), "=r"(r[2]), "=r"(r[3]) : "r"(addr));
}
__device__ __forceinline__ void mma16816(float d[4], const uint32_t a[4], uint32_t b0, uint32_t b1) {
    asm volatile("mma.sync.aligned.m16n8k16.row.col.f32.bf16.bf16.f32 "
        "{%0,%1,%2,%3}, {%4,%5,%6,%7}, {%8,%9}, {%0,%1,%2,%3};"
        : "+f"(d[0]), "+f"(d[1]), "+f"(d[2]), "+f"(d[3])
        : "r"(a[0]), "r"(a[1]), "r"(a[2]), "r"(a[3]), "r"(b0), "r"(b1));
}
__device__ __forceinline__ unsigned pack_hl(float v) {
    __nv_bfloat16 h = __float2bfloat16(v);
    float r = v - __bfloat162float(h);
    __nv_bfloat16 l = __float2bfloat16(r);
    return (unsigned)__bfloat16_as_ushort(h) | ((unsigned)__bfloat16_as_ushort(l) << 16);
}

// smem layout for body kernel (all 1024-aligned)
#define SM_WS 0               // 18 x 8192 = 147456
#define SM_AH 147456          // 23552
#define SM_AL 171008          // 23552
#define SMEM_BODY 194560

// ---------------- weight prep: [l][b][tap][ic][oc], cw folded, bf16 split ----
__global__ void prep_kernel(const float* __restrict__ bw, float cw) {
    int idx = blockIdx.x * blockDim.x + threadIdx.x;
    const int N = 5 * 16 * 9 * 64 * 64;
    if (idx >= N) return;
    int oc = idx & 63;
    int ic = (idx >> 6) & 63;
    int tap = (idx >> 12) % 9;
    int rest = idx / (9 * 64 * 64);   // l*16+b
    float v = bw[(((size_t)rest * 64 + oc) * 64 + ic) * 9 + tap] * cw;
    __nv_bfloat16 h = __float2bfloat16(v);
    __nv_bfloat16 l = __float2bfloat16(v - __bfloat162float(h));
    g_wth[idx] = h;
    g_wtl[idx] = l;
}

// ---------------- head (scalar fp32, writes packed NHWC) ----------------
__global__ __launch_bounds__(256)
void head_kernel(const float* __restrict__ noise, const float* __restrict__ hw,
                 const float* __restrict__ hb, unsigned* __restrict__ ohl,
                 float cw, float cb)
{
    const int Sout = 268;
    int b = blockIdx.z >> 2;
    int oc0 = (blockIdx.z & 3) << 4;
    int tx0 = blockIdx.x * 32, ty0 = blockIdx.y * 8;
    int tid = threadIdx.x, tx = tid & 31, ty = tid >> 5;

    __shared__ __align__(16) float ws[3 * 9 * 16];
    __shared__ float xs[3 * 10 * 34];

    for (int i = tid; i < 3 * 144; i += 256) {
        int oc = i & 15, k = (i >> 4) % 9, ic = i / 144;
        ws[i] = hw[((b * 64 + oc0 + oc) * 3 + ic) * 9 + k];
    }
    for (int i = tid; i < 3 * 340; i += 256) {
        int ic = i / 340, rem = i % 340, r = rem / 34, c = rem % 34;
        int gy = ty0 + r - 7, gx = tx0 + c - 7;
        float v = 0.f;
        if (gy >= 0 && gy < 256 && gx >= 0 && gx < 256)
            v = noise[((size_t)(b * 3 + ic) * 256 + gy) * 256 + gx];
        xs[i] = v;
    }
    __syncthreads();

    float acc[16];
#pragma unroll
    for (int o = 0; o < 16; o++) acc[o] = 0.f;
#pragma unroll
    for (int ic = 0; ic < 3; ic++) {
        const float* xp = xs + ic * 340 + ty * 34 + tx;
        float xv[9];
#pragma unroll
        for (int ky = 0; ky < 3; ky++)
#pragma unroll
            for (int kx = 0; kx < 3; kx++) xv[ky * 3 + kx] = xp[ky * 34 + kx];
        const float4* wp = (const float4*)(ws + ic * 144);
#pragma unroll
        for (int k = 0; k < 9; k++) {
#pragma unroll
            for (int q = 0; q < 4; q++) {
                float4 w4 = wp[k * 4 + q];
                acc[q * 4 + 0] = fmaf(xv[k], w4.x, acc[q * 4 + 0]);
                acc[q * 4 + 1] = fmaf(xv[k], w4.y, acc[q * 4 + 1]);
                acc[q * 4 + 2] = fmaf(xv[k], w4.z, acc[q * 4 + 2]);
                acc[q * 4 + 3] = fmaf(xv[k], w4.w, acc[q * 4 + 3]);
            }
        }
    }

    int ox = tx0 + tx, oy = ty0 + ty;
    if (ox < Sout && oy < Sout) {
        __align__(16) unsigned p16[16];
#pragma unroll
        for (int o = 0; o < 16; o++) {
            float v = acc[o] * cw + hb[b * 64 + oc0 + o] * cb;
            v = v > 0.f ? v : 0.02f * v;
            p16[o] = pack_hl(v);
        }
        size_t obase = ((size_t)b * (Sout * Sout) + (size_t)oy * Sout + ox) * 64 + oc0;
        uint4* d = (uint4*)(ohl + obase);
        d[0] = ((uint4*)p16)[0]; d[1] = ((uint4*)p16)[1];
        d[2] = ((uint4*)p16)[2]; d[3] = ((uint4*)p16)[3];
    }
}

// ---------------- body (mma.sync bf16 3-term split) ----------------
__global__ __launch_bounds__(256, 1)
void body_mma_kernel(const unsigned* __restrict__ in_hl,
                     const __nv_bfloat16* __restrict__ wth,   // [16][9][64 ic][64 oc] layer slice
                     const __nv_bfloat16* __restrict__ wtl,
                     const float* __restrict__ bias,          // [16][64]
                     unsigned* __restrict__ out_hl,
                     float* __restrict__ out_f32,
                     int Sin, int f32mode, float cb)
{
    extern __shared__ __align__(1024) char smem[];
    const int Sout = Sin - 2;
    const int b = blockIdx.z, slot = blockIdx.x;
    const int tid = threadIdx.x, wid = tid >> 5, lane = tid & 31;
    const int wm = wid & 3, wn = wid >> 2;
    uint32_t sbase = smem_u32(smem);

    // stage all weights: [tap][half][ic 64][128B oc], SW128-swizzled
    {
        const __nv_bfloat16* whb = wth + (size_t)b * 9 * 4096;
        const __nv_bfloat16* wlb = wtl + (size_t)b * 9 * 4096;
        for (int i = tid; i < 9216; i += 256) {
            int j = i & 511, th = i >> 9;
            int ic = j >> 3, q = j & 7;
            int tap = th >> 1, h = th & 1;
            const uint4* src = (const uint4*)((h ? wlb : whb) + ((size_t)tap * 64 + ic) * 64) + q;
            *(uint4*)(smem + SM_WS + th * 8192 + swz(ic * 128 + q * 16)) = *src;
        }
    }

    // per-thread bias (8 oc values)
    float bv[8];
#pragma unroll
    for (int nt = 0; nt < 4; nt++) {
        int oc = wn * 32 + nt * 8 + (lane & 3) * 2;
        bv[nt * 2 + 0] = bias[b * 64 + oc] * cb;
        bv[nt * 2 + 1] = bias[b * 64 + oc + 1] * cb;
    }

    const unsigned* ihl = in_hl + (size_t)b * Sin * Sin * 64;
    const int nrt = (Sout + 7) >> 3, nct = (Sout + 15) >> 4;
    const int ntiles = nrt * nct;
    const size_t Spo = (size_t)Sout * Sout;

    const int laneA = (lane & 15) * 128 + (lane >> 4) * 16;
    // B: row = k (ic), col bytes = oc; lanes 0-15 rows, lanes 16-31 +16B (oc+8)
    const int laneBrow = (lane & 15) * 128 + (lane >> 4) * 16 + wn * 64;

    for (int tt = slot; tt < ntiles; tt += 9) {
        int rt = tt / nct, ct = tt - rt * nct;
        int oy0 = rt * 8, ox0 = ct * 16;

        __syncthreads();
        // gather slab: 10 rows x 18 cols input pixels, unpack to hi/lo halves
        for (int i = tid; i < 2880; i += 256) {
            int e = i >> 4, q = i & 15;
            int er = e / 18, ec = e - er * 18;
            int iy = oy0 + er, ix = ox0 + ec;
            uint4 w = make_uint4(0u, 0u, 0u, 0u);
            if (iy < Sin && ix < Sin)
                w = *(const uint4*)(ihl + ((size_t)iy * Sin + ix) * 64 + q * 4);
            unsigned h0, h1, l0, l1;
            asm("prmt.b32 %0, %1, %2, 0x5410;" : "=r"(h0) : "r"(w.x), "r"(w.y));
            asm("prmt.b32 %0, %1, %2, 0x7632;" : "=r"(l0) : "r"(w.x), "r"(w.y));
            asm("prmt.b32 %0, %1, %2, 0x5410;" : "=r"(h1) : "r"(w.z), "r"(w.w));
            asm("prmt.b32 %0, %1, %2, 0x7632;" : "=r"(l1) : "r"(w.z), "r"(w.w));
            uint32_t off = swz((uint32_t)(e * 128 + q * 8));
            *(uint2*)(smem + SM_AH + off) = make_uint2(h0, h1);
            *(uint2*)(smem + SM_AL + off) = make_uint2(l0, l1);
        }
        __syncthreads();

        float acc[2][4][4];
#pragma unroll
        for (int mt = 0; mt < 2; mt++)
#pragma unroll
            for (int j = 0; j < 4; j++)
#pragma unroll
                for (int r = 0; r < 4; r++) acc[mt][j][r] = 0.f;

#pragma unroll
        for (int ky = 0; ky < 3; ky++) {
#pragma unroll
            for (int kx = 0; kx < 3; kx++) {
                int tap = ky * 3 + kx;
                uint32_t wtile = sbase + SM_WS + tap * 16384;
#pragma unroll
                for (int kc = 0; kc < 4; kc++) {
                    uint32_t a_h[2][4], a_l[2][4];
#pragma unroll
                    for (int mt = 0; mt < 2; mt++) {
                        int ebase = ((wm * 2 + mt + ky) * 18 + kx) * 128 + kc * 32;
                        uint32_t off = swz((uint32_t)(ebase + laneA));
                        ldsm4(a_h[mt], sbase + SM_AH + off);
                        ldsm4(a_l[mt], sbase + SM_AL + off);
                    }
                    // B: rows kc*16 + (lane&15); cols: wn*64 + nt*32 + (lane>>4)*16
                    uint32_t b_h[2][4], b_l[2][4];
#pragma unroll
                    for (int nt = 0; nt < 2; nt++) {
                        uint32_t off = swz((uint32_t)(kc * 16 * 128 + laneBrow + nt * 32));
                        ldsm4t(b_h[nt], wtile + off);
                        ldsm4t(b_l[nt], wtile + 8192 + off);
                    }
#pragma unroll
                    for (int mt = 0; mt < 2; mt++) {
#pragma unroll
                        for (int j = 0; j < 4; j++) {
                            uint32_t bh0 = b_h[j >> 1][(j & 1) * 2];
                            uint32_t bh1 = b_h[j >> 1][(j & 1) * 2 + 1];
                            uint32_t bl0 = b_l[j >> 1][(j & 1) * 2];
                            uint32_t bl1 = b_l[j >> 1][(j & 1) * 2 + 1];
                            mma16816(acc[mt][j], a_h[mt], bh0, bh1);
                            mma16816(acc[mt][j], a_l[mt], bh0, bh1);
                            mma16816(acc[mt][j], a_h[mt], bl0, bl1);
                        }
                    }
                }
            }
        }

        // epilogue: bias + leaky, pack/store
#pragma unroll
        for (int mt = 0; mt < 2; mt++) {
            int oy = oy0 + wm * 2 + mt;
            if (oy >= Sout) continue;
#pragma unroll
            for (int rs = 0; rs < 2; rs++) {
                int c = (lane >> 2) + rs * 8;
                int ox = ox0 + c;
                if (ox >= Sout) continue;
                size_t pix = (size_t)oy * Sout + ox;
                size_t eoff = ((size_t)b * Spo + pix) * 64 + wn * 32 + (lane & 3) * 2;
                if (f32mode) {
                    float* dst = out_f32 + eoff;
#pragma unroll
                    for (int nt = 0; nt < 4; nt++) {
                        float v0 = acc[mt][nt][rs * 2 + 0] + bv[nt * 2 + 0];
                        float v1 = acc[mt][nt][rs * 2 + 1] + bv[nt * 2 + 1];
                        v0 = v0 > 0.f ? v0 : 0.02f * v0;
                        v1 = v1 > 0.f ? v1 : 0.02f * v1;
                        *(float2*)(dst + nt * 8) = make_float2(v0, v1);
                    }
                } else {
                    unsigned* dst = out_hl + eoff;
#pragma unroll
                    for (int nt = 0; nt < 4; nt++) {
                        float v0 = acc[mt][nt][rs * 2 + 0] + bv[nt * 2 + 0];
                        float v1 = acc[mt][nt][rs * 2 + 1] + bv[nt * 2 + 1];
                        v0 = v0 > 0.f ? v0 : 0.02f * v0;
                        v1 = v1 > 0.f ? v1 : 0.02f * v1;
                        *(uint2*)(dst + nt * 8) = make_uint2(pack_hl(v0), pack_hl(v1));
                    }
                }
            }
        }
    }
}

// ---------------- tail (scalar, reads NHWC fp32) ----------------
__global__ __launch_bounds__(256)
void tail_kernel(const float* __restrict__ in,   // [16][258*258][64] NHWC
                 const float* __restrict__ w, const float* __restrict__ bias,
                 float* __restrict__ out, float cw, float cb)
{
    extern __shared__ float sm[];
    float* ws = sm;              // 64*27
    float* xs = sm + 1728;       // 64 ic x 340 pixels
    const int Sin = 258, Sout = 256;
    int b = blockIdx.z;
    int tx0 = blockIdx.x * 32, ty0 = blockIdx.y * 8;
    int tid = threadIdx.x, tx = tid & 31, ty = tid >> 5;

    for (int i = tid; i < 64 * 27; i += 256) {
        int oc = i % 3, k = (i / 3) % 9, ic = i / 27;
        ws[i] = w[((b * 3 + oc) * 64 + ic) * 9 + k];
    }
    const float* inb = in + (size_t)b * Sin * Sin * 64;
    for (int i = tid; i < 5440; i += 256) {
        int p = i >> 4, q = i & 15;
        int py = p / 34, px = p - py * 34;
        float4 v = *(const float4*)(inb + ((size_t)(ty0 + py) * Sin + tx0 + px) * 64 + q * 4);
        int icb = q * 4;
        xs[(icb + 0) * 340 + p] = v.x;
        xs[(icb + 1) * 340 + p] = v.y;
        xs[(icb + 2) * 340 + p] = v.z;
        xs[(icb + 3) * 340 + p] = v.w;
    }
    __syncthreads();

    float acc[3] = {0.f, 0.f, 0.f};
#pragma unroll 4
    for (int ic = 0; ic < 64; ic++) {
        const float* xp = xs + ic * 340 + ty * 34 + tx;
        float xv[9];
#pragma unroll
        for (int ky = 0; ky < 3; ky++)
#pragma unroll
            for (int kx = 0; kx < 3; kx++) xv[ky * 3 + kx] = xp[ky * 34 + kx];
        const float* wp = ws + ic * 27;
#pragma unroll
        for (int k = 0; k < 9; k++)
#pragma unroll
            for (int o = 0; o < 3; o++) acc[o] = fmaf(xv[k], wp[k * 3 + o], acc[o]);
    }

    int ox = tx0 + tx, oy = ty0 + ty;
    size_t obase = ((size_t)(b * 3)) * 65536 + (size_t)oy * 256 + ox;
#pragma unroll
    for (int o = 0; o < 3; o++)
        out[obase + (size_t)o * 65536] = tanhf(acc[o] * cw + bias[b * 3 + o] * cb);
}

// ---------------- launch ----------------
extern "C" void kernel_launch(void* const* d_in, const int* in_sizes, int n_in,
                              void* d_out, int out_size)
{
    const float* noise  = (const float*)d_in[0];
    const float* head_w = (const float*)d_in[1];
    const float* head_b = (const float*)d_in[2];
    const float* body_w = (const float*)d_in[3];
    const float* body_b = (const float*)d_in[4];
    const float* tail_w = (const float*)d_in[5];
    const float* tail_b = (const float*)d_in[6];
    float* out = (float*)d_out;

    unsigned *hlA, *hlB;
    float* f32;
    __nv_bfloat16 *wth, *wtl;
    cudaGetSymbolAddress((void**)&hlA, g_hlA);
    cudaGetSymbolAddress((void**)&hlB, g_hlB);
    cudaGetSymbolAddress((void**)&f32, g_f32);
    cudaGetSymbolAddress((void**)&wth, g_wth);
    cudaGetSymbolAddress((void**)&wtl, g_wtl);

    cudaFuncSetAttribute(body_mma_kernel, cudaFuncAttributeMaxDynamicSharedMemorySize, SMEM_BODY);
    cudaFuncSetAttribute(tail_kernel, cudaFuncAttributeMaxDynamicSharedMemorySize, 94208);

    const double lr_gain = sqrt(2.0 / (1.0 + 0.02 * 0.02));
    const float cw_head = (float)(lr_gain / sqrt(27.0));
    const float cb_head = (float)(1.0 / sqrt(3.0));
    const float cw_body = (float)(lr_gain / 24.0);
    const float cb_body = 0.125f;
    const float cw_tail = (float)((5.0 / 3.0) / 24.0);
    const float cb_tail = 0.125f;

    // body weight prep (fold cw, bf16 split, k-major)
    {
        int N = 5 * 16 * 9 * 64 * 64;
        prep_kernel<<<(N + 255) / 256, 256>>>(body_w, cw_body);
    }

    // head -> hlA (268)
    {
        dim3 grid((268 + 31) / 32, (268 + 7) / 8, BATCH * 4);
        head_kernel<<<grid, 256>>>(noise, head_w, head_b, hlA, cw_head, cb_head);
    }

    // 5 body layers, ping-pong packed buffers; last writes fp32 NHWC
    unsigned *src = hlA, *dst = hlB;
    int Sin = 268;
    for (int l = 0; l < 5; l++) {
        int f32mode = (l == 4);
        dim3 grid(9, 1, BATCH);
        const __nv_bfloat16* wh_l = wth + (size_t)l * 16 * 9 * 4096;
        const __nv_bfloat16* wl_l = wtl + (size_t)l * 16 * 9 * 4096;
        const float* bias_l = body_b + (size_t)l * 16 * 64;
        body_mma_kernel<<<grid, 256, SMEM_BODY>>>(src, wh_l, wl_l, bias_l,
                                                  dst, f32, Sin, f32mode, cb_body);
        unsigned* t = src; src = dst; dst = t;
        Sin -= 2;
    }

    // tail: f32 NHWC (258) -> out (256)
    {
        dim3 grid(256 / 32, 256 / 8, BATCH);
        tail_kernel<<<grid, 256, 94208>>>(f32, tail_w, tail_b, out, cw_tail, cb_tail);
    }
}

// round 6
// speedup vs baseline: 4.4845x; 1.0281x over previous
#include <cuda_runtime.h>
#include <cuda_bf16.h>
#include <math.h>
#include <stdint.h>

#define BATCH 16
#define MAXPIX (268u * 268u)

// activations NHWC bf16, separate hi/lo, ping-pong pairs
__device__ __nv_bfloat16 g_ah[16u * MAXPIX * 64u];
__device__ __nv_bfloat16 g_al[16u * MAXPIX * 64u];
__device__ __nv_bfloat16 g_bh[16u * MAXPIX * 64u];
__device__ __nv_bfloat16 g_bl[16u * MAXPIX * 64u];
// pre-split body weights, K-MAJOR: [5][16][tap 9][ic 64][oc 64] bf16
__device__ __nv_bfloat16 g_wth[5u * 16u * 9u * 64u * 64u];
__device__ __nv_bfloat16 g_wtl[5u * 16u * 9u * 64u * 64u];

// ---------------- helpers ----------------
__device__ __forceinline__ uint32_t smem_u32(const void* p) {
    uint32_t a;
    asm("{ .reg .u64 t; cvta.to.shared.u64 t, %1; cvt.u32.u64 %0, t; }" : "=r"(a) : "l"(p));
    return a;
}
__device__ __forceinline__ uint32_t swz(uint32_t o) { return o ^ ((o >> 3) & 0x70); }

__device__ __forceinline__ void ldsm4(uint32_t r[4], uint32_t addr) {
    asm volatile("ldmatrix.sync.aligned.m8n8.x4.shared.b16 {%0,%1,%2,%3}, [%4];"
        : "=r"(r[0]), "=r"(r[1]), "=r"(r[2]), "=r"(r[3]) : "r"(addr));
}
__device__ __forceinline__ void ldsm4t(uint32_t r[4], uint32_t addr) {
    asm volatile("ldmatrix.sync.aligned.m8n8.x4.trans.shared.b16 {%0,%1,%2,%3}, [%4];"
        : "=r"(r[0]), "=r"(r[1]), "=r"(r[2]), "=r"(r[3]) : "r"(addr));
}
__device__ __forceinline__ void mma16816(float d[4], const uint32_t a[4], uint32_t b0, uint32_t b1) {
    asm volatile("mma.sync.aligned.m16n8k16.row.col.f32.bf16.bf16.f32 "
        "{%0,%1,%2,%3}, {%4,%5,%6,%7}, {%8,%9}, {%0,%1,%2,%3};"
        : "+f"(d[0]), "+f"(d[1]), "+f"(d[2]), "+f"(d[3])
        : "r"(a[0]), "r"(a[1]), "r"(a[2]), "r"(a[3]), "r"(b0), "r"(b1));
}
__device__ __forceinline__ void cp16(uint32_t dst, const void* src) {
    asm volatile("cp.async.cg.shared.global [%0], [%1], 16;" :: "r"(dst), "l"(src) : "memory");
}
#define CP_COMMIT() asm volatile("cp.async.commit_group;" ::: "memory")
#define CP_WAIT(n)  asm volatile("cp.async.wait_group %0;" :: "n"(n) : "memory")

// smem layout for body kernel
#define SM_WS   0          // 18 x 8192 = 147456
#define SM_HI0  147456     // 23040 (pad to 23552)
#define SM_HI1  171008
#define SM_LO   194560
#define SMEM_BODY 218112

// ---------------- weight prep: [l][b][tap][ic][oc], cw folded, bf16 split ----
__global__ void prep_kernel(const float* __restrict__ bw, float cw) {
    int idx = blockIdx.x * blockDim.x + threadIdx.x;
    const int N = 5 * 16 * 9 * 64 * 64;
    if (idx >= N) return;
    int oc = idx & 63;
    int ic = (idx >> 6) & 63;
    int tap = (idx >> 12) % 9;
    int rest = idx / (9 * 64 * 64);   // l*16+b
    float v = bw[(((size_t)rest * 64 + oc) * 64 + ic) * 9 + tap] * cw;
    __nv_bfloat16 h = __float2bfloat16(v);
    __nv_bfloat16 l = __float2bfloat16(v - __bfloat162float(h));
    g_wth[idx] = h;
    g_wtl[idx] = l;
}

// ---------------- head (scalar fp32, writes NHWC hi/lo) ----------------
__global__ __launch_bounds__(256)
void head_kernel(const float* __restrict__ noise, const float* __restrict__ hw,
                 const float* __restrict__ hb, __nv_bfloat16* __restrict__ oh,
                 __nv_bfloat16* __restrict__ ol, float cw, float cb)
{
    const int Sout = 268;
    int b = blockIdx.z >> 2;
    int oc0 = (blockIdx.z & 3) << 4;
    int tx0 = blockIdx.x * 32, ty0 = blockIdx.y * 8;
    int tid = threadIdx.x, tx = tid & 31, ty = tid >> 5;

    __shared__ __align__(16) float ws[3 * 9 * 16];
    __shared__ float xs[3 * 10 * 34];

    for (int i = tid; i < 3 * 144; i += 256) {
        int oc = i & 15, k = (i >> 4) % 9, ic = i / 144;
        ws[i] = hw[((b * 64 + oc0 + oc) * 3 + ic) * 9 + k];
    }
    for (int i = tid; i < 3 * 340; i += 256) {
        int ic = i / 340, rem = i % 340, r = rem / 34, c = rem % 34;
        int gy = ty0 + r - 7, gx = tx0 + c - 7;
        float v = 0.f;
        if (gy >= 0 && gy < 256 && gx >= 0 && gx < 256)
            v = noise[((size_t)(b * 3 + ic) * 256 + gy) * 256 + gx];
        xs[i] = v;
    }
    __syncthreads();

    float acc[16];
#pragma unroll
    for (int o = 0; o < 16; o++) acc[o] = 0.f;
#pragma unroll
    for (int ic = 0; ic < 3; ic++) {
        const float* xp = xs + ic * 340 + ty * 34 + tx;
        float xv[9];
#pragma unroll
        for (int ky = 0; ky < 3; ky++)
#pragma unroll
            for (int kx = 0; kx < 3; kx++) xv[ky * 3 + kx] = xp[ky * 34 + kx];
        const float4* wp = (const float4*)(ws + ic * 144);
#pragma unroll
        for (int k = 0; k < 9; k++) {
#pragma unroll
            for (int q = 0; q < 4; q++) {
                float4 w4 = wp[k * 4 + q];
                acc[q * 4 + 0] = fmaf(xv[k], w4.x, acc[q * 4 + 0]);
                acc[q * 4 + 1] = fmaf(xv[k], w4.y, acc[q * 4 + 1]);
                acc[q * 4 + 2] = fmaf(xv[k], w4.z, acc[q * 4 + 2]);
                acc[q * 4 + 3] = fmaf(xv[k], w4.w, acc[q * 4 + 3]);
            }
        }
    }

    int ox = tx0 + tx, oy = ty0 + ty;
    if (ox < Sout && oy < Sout) {
        __align__(16) __nv_bfloat16 h16[16], l16[16];
#pragma unroll
        for (int o = 0; o < 16; o++) {
            float v = acc[o] * cw + hb[b * 64 + oc0 + o] * cb;
            v = v > 0.f ? v : 0.02f * v;
            h16[o] = __float2bfloat16(v);
            l16[o] = __float2bfloat16(v - __bfloat162float(h16[o]));
        }
        size_t obase = ((size_t)b * (Sout * Sout) + (size_t)oy * Sout + ox) * 64 + oc0;
        uint4* dh = (uint4*)(oh + obase);
        uint4* dl = (uint4*)(ol + obase);
        dh[0] = ((uint4*)h16)[0]; dh[1] = ((uint4*)h16)[1];
        dl[0] = ((uint4*)l16)[0]; dl[1] = ((uint4*)l16)[1];
    }
}

// ---------------- body A-slab gather via cp.async ----------------
__device__ __forceinline__ void gather_cp(uint32_t dst, const __nv_bfloat16* __restrict__ src,
                                          int oy0, int ox0, int Sin, int tid)
{
    // slab: 10 rows x 18 px x 64 ch bf16 -> 1440 16B chunks, SW128 swizzled
    for (int i = tid; i < 1440; i += 256) {
        int e = i >> 3, q = i & 7;
        int er = e / 18, ec = e - er * 18;
        int iy = oy0 + er; if (iy > Sin - 1) iy = Sin - 1;
        int ix = ox0 + ec; if (ix > Sin - 1) ix = Sin - 1;
        const void* s = src + ((size_t)iy * Sin + ix) * 64 + q * 8;
        cp16(dst + swz((uint32_t)(e * 128 + q * 16)), s);
    }
    CP_COMMIT();
}

// ---------------- body (mma.sync bf16 3-term split, cp.async pipelined) ------
__global__ __launch_bounds__(256, 1)
void body_mma_kernel(const __nv_bfloat16* __restrict__ in_h,
                     const __nv_bfloat16* __restrict__ in_l,
                     const __nv_bfloat16* __restrict__ wth,   // [16][9][64 ic][64 oc]
                     const __nv_bfloat16* __restrict__ wtl,
                     const float* __restrict__ bias,          // [16][64]
                     __nv_bfloat16* __restrict__ out_h,
                     __nv_bfloat16* __restrict__ out_l,
                     int Sin, float cb)
{
    extern __shared__ __align__(1024) char smem[];
    const int Sout = Sin - 2;
    const int b = blockIdx.z, slot = blockIdx.x;
    const int tid = threadIdx.x, wid = tid >> 5, lane = tid & 31;
    const int wm = wid & 3, wn = wid >> 2;
    uint32_t sbase = smem_u32(smem);
    const uint32_t HI[2] = { sbase + SM_HI0, sbase + SM_HI1 };
    const uint32_t LO = sbase + SM_LO;

    // stage weights: [tap][half][ic 64][128B oc], SW128-swizzled
    {
        const __nv_bfloat16* whb = wth + (size_t)b * 9 * 4096;
        const __nv_bfloat16* wlb = wtl + (size_t)b * 9 * 4096;
        for (int i = tid; i < 9216; i += 256) {
            int j = i & 511, th = i >> 9;
            int ic = j >> 3, q = j & 7;
            int tap = th >> 1, h = th & 1;
            const uint4* src = (const uint4*)((h ? wlb : whb) + ((size_t)tap * 64 + ic) * 64) + q;
            *(uint4*)(smem + SM_WS + th * 8192 + swz(ic * 128 + q * 16)) = *src;
        }
    }

    // per-thread bias
    float bv[8];
#pragma unroll
    for (int nt = 0; nt < 4; nt++) {
        int oc = wn * 32 + nt * 8 + (lane & 3) * 2;
        bv[nt * 2 + 0] = bias[b * 64 + oc] * cb;
        bv[nt * 2 + 1] = bias[b * 64 + oc + 1] * cb;
    }

    const __nv_bfloat16* ih = in_h + (size_t)b * Sin * Sin * 64;
    const __nv_bfloat16* il = in_l + (size_t)b * Sin * Sin * 64;
    const int nrt = (Sout + 7) >> 3, nct = (Sout + 15) >> 4;
    const int ntiles = nrt * nct;
    const size_t Spo = (size_t)Sout * Sout;

    const int laneA = (lane & 15) * 128 + (lane >> 4) * 16;
    const int laneBrow = (lane & 15) * 128 + (lane >> 4) * 16 + wn * 64;

    int s = 0;
    // prologue: prefetch hi slab of first tile
    {
        int t0 = slot;
        if (t0 < ntiles) {
            int rt = t0 / nct, ct = t0 - rt * nct;
            gather_cp(HI[0], ih, rt * 8, ct * 16, Sin, tid);
        } else {
            CP_COMMIT();
        }
    }

    for (int tt = slot; tt < ntiles; tt += 9) {
        int rt = tt / nct, ct = tt - rt * nct;
        int oy0 = rt * 8, ox0 = ct * 16;
        int tn = (tt + 9 < ntiles) ? tt + 9 : tt;
        int rtn = tn / nct, ctn = tn - rtn * nct;

        __syncthreads();                       // (a) lo + hi[1-s] free
        gather_cp(LO, il, oy0, ox0, Sin, tid);           // group: lo(t)
        gather_cp(HI[1 - s], ih, rtn * 8, ctn * 16, Sin, tid); // group: hi(t+1)
        CP_WAIT(2); __syncthreads();           // (b) hi[s] ready

        float acc[2][4][4];
#pragma unroll
        for (int mt = 0; mt < 2; mt++)
#pragma unroll
            for (int j = 0; j < 4; j++)
#pragma unroll
                for (int r = 0; r < 4; r++) acc[mt][j][r] = 0.f;

        // phase 1: AhBh + AhBl
#pragma unroll
        for (int ky = 0; ky < 3; ky++) {
#pragma unroll
            for (int kx = 0; kx < 3; kx++) {
                uint32_t wtile = sbase + SM_WS + (ky * 3 + kx) * 16384;
#pragma unroll
                for (int kc = 0; kc < 4; kc++) {
                    uint32_t a_h[2][4];
#pragma unroll
                    for (int mt = 0; mt < 2; mt++) {
                        int ebase = ((wm * 2 + mt + ky) * 18 + kx) * 128 + kc * 32;
                        ldsm4(a_h[mt], HI[s] + swz((uint32_t)(ebase + laneA)));
                    }
                    uint32_t b_h[2][4], b_l[2][4];
#pragma unroll
                    for (int nt = 0; nt < 2; nt++) {
                        uint32_t off = swz((uint32_t)(kc * 2048 + laneBrow + nt * 32));
                        ldsm4t(b_h[nt], wtile + off);
                        ldsm4t(b_l[nt], wtile + 8192 + off);
                    }
#pragma unroll
                    for (int mt = 0; mt < 2; mt++) {
#pragma unroll
                        for (int j = 0; j < 4; j++) {
                            uint32_t bh0 = b_h[j >> 1][(j & 1) * 2];
                            uint32_t bh1 = b_h[j >> 1][(j & 1) * 2 + 1];
                            uint32_t bl0 = b_l[j >> 1][(j & 1) * 2];
                            uint32_t bl1 = b_l[j >> 1][(j & 1) * 2 + 1];
                            mma16816(acc[mt][j], a_h[mt], bh0, bh1);
                            mma16816(acc[mt][j], a_h[mt], bl0, bl1);
                        }
                    }
                }
            }
        }

        CP_WAIT(1); __syncthreads();           // (c) lo ready

        // phase 2: AlBh
#pragma unroll
        for (int ky = 0; ky < 3; ky++) {
#pragma unroll
            for (int kx = 0; kx < 3; kx++) {
                uint32_t wtile = sbase + SM_WS + (ky * 3 + kx) * 16384;
#pragma unroll
                for (int kc = 0; kc < 4; kc++) {
                    uint32_t a_l[2][4];
#pragma unroll
                    for (int mt = 0; mt < 2; mt++) {
                        int ebase = ((wm * 2 + mt + ky) * 18 + kx) * 128 + kc * 32;
                        ldsm4(a_l[mt], LO + swz((uint32_t)(ebase + laneA)));
                    }
                    uint32_t b_h[2][4];
#pragma unroll
                    for (int nt = 0; nt < 2; nt++) {
                        uint32_t off = swz((uint32_t)(kc * 2048 + laneBrow + nt * 32));
                        ldsm4t(b_h[nt], wtile + off);
                    }
#pragma unroll
                    for (int mt = 0; mt < 2; mt++) {
#pragma unroll
                        for (int j = 0; j < 4; j++) {
                            uint32_t bh0 = b_h[j >> 1][(j & 1) * 2];
                            uint32_t bh1 = b_h[j >> 1][(j & 1) * 2 + 1];
                            mma16816(acc[mt][j], a_l[mt], bh0, bh1);
                        }
                    }
                }
            }
        }

        // epilogue: bias + leaky, split to hi/lo, store
#pragma unroll
        for (int mt = 0; mt < 2; mt++) {
            int oy = oy0 + wm * 2 + mt;
            if (oy >= Sout) continue;
#pragma unroll
            for (int rs = 0; rs < 2; rs++) {
                int c = (lane >> 2) + rs * 8;
                int ox = ox0 + c;
                if (ox >= Sout) continue;
                size_t pix = (size_t)oy * Sout + ox;
                size_t eoff = ((size_t)b * Spo + pix) * 64 + wn * 32 + (lane & 3) * 2;
#pragma unroll
                for (int nt = 0; nt < 4; nt++) {
                    float v0 = acc[mt][nt][rs * 2 + 0] + bv[nt * 2 + 0];
                    float v1 = acc[mt][nt][rs * 2 + 1] + bv[nt * 2 + 1];
                    v0 = v0 > 0.f ? v0 : 0.02f * v0;
                    v1 = v1 > 0.f ? v1 : 0.02f * v1;
                    __nv_bfloat16 h0 = __float2bfloat16(v0);
                    __nv_bfloat16 h1 = __float2bfloat16(v1);
                    __nv_bfloat16 l0 = __float2bfloat16(v0 - __bfloat162float(h0));
                    __nv_bfloat16 l1 = __float2bfloat16(v1 - __bfloat162float(h1));
                    unsigned ph = (unsigned)__bfloat16_as_ushort(h0) | ((unsigned)__bfloat16_as_ushort(h1) << 16);
                    unsigned pl = (unsigned)__bfloat16_as_ushort(l0) | ((unsigned)__bfloat16_as_ushort(l1) << 16);
                    *(unsigned*)(out_h + eoff + nt * 8) = ph;
                    *(unsigned*)(out_l + eoff + nt * 8) = pl;
                }
            }
        }
        s ^= 1;
    }
}

// ---------------- tail (scalar, reads NHWC hi/lo) ----------------
__global__ __launch_bounds__(256)
void tail_kernel(const __nv_bfloat16* __restrict__ in_h,
                 const __nv_bfloat16* __restrict__ in_l,
                 const float* __restrict__ w, const float* __restrict__ bias,
                 float* __restrict__ out, float cw, float cb)
{
    extern __shared__ float sm[];
    float* ws = sm;              // 64*27
    float* xs = sm + 1728;       // 64 ic x 340 px
    const int Sin = 258, Sout = 256;
    int b = blockIdx.z;
    int tx0 = blockIdx.x * 32, ty0 = blockIdx.y * 8;
    int tid = threadIdx.x, tx = tid & 31, ty = tid >> 5;

    for (int i = tid; i < 64 * 27; i += 256) {
        int oc = i % 3, k = (i / 3) % 9, ic = i / 27;
        ws[i] = w[((b * 3 + oc) * 64 + ic) * 9 + k];
    }
    const __nv_bfloat16* ihb = in_h + (size_t)b * Sin * Sin * 64;
    const __nv_bfloat16* ilb = in_l + (size_t)b * Sin * Sin * 64;
    for (int i = tid; i < 2720; i += 256) {
        int p = i >> 3, g = i & 7;
        int py = p / 34, px = p - py * 34;
        size_t pb = ((size_t)(ty0 + py) * Sin + tx0 + px) * 64 + g * 8;
        uint4 H = *(const uint4*)(ihb + pb);
        uint4 L = *(const uint4*)(ilb + pb);
        const unsigned* hu = (const unsigned*)&H;
        const unsigned* lu = (const unsigned*)&L;
#pragma unroll
        for (int j = 0; j < 4; j++) {
            float2 fh = __bfloat1622float2(*(const __nv_bfloat162*)&hu[j]);
            float2 fl = __bfloat1622float2(*(const __nv_bfloat162*)&lu[j]);
            xs[(g * 8 + j * 2 + 0) * 340 + p] = fh.x + fl.x;
            xs[(g * 8 + j * 2 + 1) * 340 + p] = fh.y + fl.y;
        }
    }
    __syncthreads();

    float acc[3] = {0.f, 0.f, 0.f};
#pragma unroll 4
    for (int ic = 0; ic < 64; ic++) {
        const float* xp = xs + ic * 340 + ty * 34 + tx;
        float xv[9];
#pragma unroll
        for (int ky = 0; ky < 3; ky++)
#pragma unroll
            for (int kx = 0; kx < 3; kx++) xv[ky * 3 + kx] = xp[ky * 34 + kx];
        const float* wp = ws + ic * 27;
#pragma unroll
        for (int k = 0; k < 9; k++)
#pragma unroll
            for (int o = 0; o < 3; o++) acc[o] = fmaf(xv[k], wp[k * 3 + o], acc[o]);
    }

    int ox = tx0 + tx, oy = ty0 + ty;
    size_t obase = ((size_t)(b * 3)) * 65536 + (size_t)oy * 256 + ox;
#pragma unroll
    for (int o = 0; o < 3; o++)
        out[obase + (size_t)o * 65536] = tanhf(acc[o] * cw + bias[b * 3 + o] * cb);
}

// ---------------- launch ----------------
extern "C" void kernel_launch(void* const* d_in, const int* in_sizes, int n_in,
                              void* d_out, int out_size)
{
    const float* noise  = (const float*)d_in[0];
    const float* head_w = (const float*)d_in[1];
    const float* head_b = (const float*)d_in[2];
    const float* body_w = (const float*)d_in[3];
    const float* body_b = (const float*)d_in[4];
    const float* tail_w = (const float*)d_in[5];
    const float* tail_b = (const float*)d_in[6];
    float* out = (float*)d_out;

    __nv_bfloat16 *ah, *al, *bh, *bl, *wth, *wtl;
    cudaGetSymbolAddress((void**)&ah, g_ah);
    cudaGetSymbolAddress((void**)&al, g_al);
    cudaGetSymbolAddress((void**)&bh, g_bh);
    cudaGetSymbolAddress((void**)&bl, g_bl);
    cudaGetSymbolAddress((void**)&wth, g_wth);
    cudaGetSymbolAddress((void**)&wtl, g_wtl);

    cudaFuncSetAttribute(body_mma_kernel, cudaFuncAttributeMaxDynamicSharedMemorySize, SMEM_BODY);
    cudaFuncSetAttribute(tail_kernel, cudaFuncAttributeMaxDynamicSharedMemorySize, 94208);

    const double lr_gain = sqrt(2.0 / (1.0 + 0.02 * 0.02));
    const float cw_head = (float)(lr_gain / sqrt(27.0));
    const float cb_head = (float)(1.0 / sqrt(3.0));
    const float cw_body = (float)(lr_gain / 24.0);
    const float cb_body = 0.125f;
    const float cw_tail = (float)((5.0 / 3.0) / 24.0);
    const float cb_tail = 0.125f;

    // body weight prep (fold cw, bf16 split, k-major)
    {
        int N = 5 * 16 * 9 * 64 * 64;
        prep_kernel<<<(N + 255) / 256, 256>>>(body_w, cw_body);
    }

    // head -> (ah, al) (268)
    {
        dim3 grid((268 + 31) / 32, (268 + 7) / 8, BATCH * 4);
        head_kernel<<<grid, 256>>>(noise, head_w, head_b, ah, al, cw_head, cb_head);
    }

    // 5 body layers, ping-pong hi/lo buffers
    __nv_bfloat16 *sh = ah, *sl = al, *dh = bh, *dl = bl;
    int Sin = 268;
    for (int l = 0; l < 5; l++) {
        dim3 grid(9, 1, BATCH);
        const __nv_bfloat16* wh_l = wth + (size_t)l * 16 * 9 * 4096;
        const __nv_bfloat16* wl_l = wtl + (size_t)l * 16 * 9 * 4096;
        const float* bias_l = body_b + (size_t)l * 16 * 64;
        body_mma_kernel<<<grid, 256, SMEM_BODY>>>(sh, sl, wh_l, wl_l, bias_l,
                                                  dh, dl, Sin, cb_body);
        __nv_bfloat16* t;
        t = sh; sh = dh; dh = t;
        t = sl; sl = dl; dl = t;
        Sin -= 2;
    }

    // tail: (sh, sl) 258 -> out 256
    {
        dim3 grid(256 / 32, 256 / 8, BATCH);
        tail_kernel<<<grid, 256, 94208>>>(sh, sl, tail_w, tail_b, out, cw_tail, cb_tail);
    }
}